// round 8
// baseline (speedup 1.0000x reference)
#include <cuda_runtime.h>

// frames: [4, B=8, C=64, H=160, W=160] fp32 ; out: [B, 256, H, W] fp32
// out_i[c,p] = sum_j exp(v_i[c,p]*v_j[c,p]) * v_j[c,p] / Z_i(p)
// Z_i(p) = sum_{j,c} exp(v_i[c,p]*v_j[c,p]);  exp matrix symmetric in (i,j).
//
// Thread layout (256 thr/block, tile = 32 pixels):
//   q     = tid & 7   -> pixel group (4 consecutive px, float4)
//   slice = tid >> 3  -> 0..31, owns channels {2*slice, 2*slice+1}
// All gmem traffic is LDG.128 / STG.128, fully coalesced.
// No smem staging: inputs go straight to registers (each value has a single
// consumer thread). Only the tiny Z reduction uses smem.

#define HW_  25600
#define B_   8
#define NTHR 256

__device__ __forceinline__ float ex2f(float x) {
    float y;
    asm("ex2.approx.ftz.f32 %0, %1;" : "=f"(y) : "f"(x));
    return y;
}

__global__ __launch_bounds__(NTHR, 2)
void frame_attn_kernel(const float* __restrict__ frames, float* __restrict__ out)
{
    __shared__ float4 szp[8][4][8];   // [warp][head i][q] partial Z (4 px each)
    __shared__ float4 srz[4][8];      // [head i][q] reciprocal Z

    const int tid   = threadIdx.x;
    const int q     = tid & 7;
    const int slice = tid >> 3;       // 0..31
    const int w     = tid >> 5;       // warp 0..7
    const int lane  = tid & 31;

    const int b   = blockIdx.x / (HW_ / 32);
    const int p0  = (blockIdx.x % (HW_ / 32)) * 32 + q * 4;   // this thread's 4 px
    const int c0  = slice * 2;

    // ---- front-batched vector loads: 8x LDG.128 ----
    const float4* fp = (const float4*)frames;
    float v[4][2][4];
    #pragma unroll
    for (int j = 0; j < 4; ++j)
        #pragma unroll
        for (int cc = 0; cc < 2; ++cc) {
            float4 t = fp[((size_t)(j * B_ + b) * 64 + c0 + cc) * (HW_ / 4) + (p0 >> 2)];
            v[j][cc][0] = t.x; v[j][cc][1] = t.y; v[j][cc][2] = t.z; v[j][cc][3] = t.w;
        }

    // ---- compute: 10 symmetric pairs per (channel, pixel) ----
    float n[4][2][4];                 // numerators (head, channel, px)
    float z[4][4];                    // per-head Z partials (head, px)
    #pragma unroll
    for (int i = 0; i < 4; ++i)
        #pragma unroll
        for (int e = 0; e < 4; ++e) z[i][e] = 0.0f;

    const float LOG2E = 1.4426950408889634f;

    #pragma unroll
    for (int cc = 0; cc < 2; ++cc) {
        #pragma unroll
        for (int e = 0; e < 4; ++e) {
            float vk[4], wk[4];
            #pragma unroll
            for (int j = 0; j < 4; ++j) {
                vk[j] = v[j][cc][e];
                wk[j] = vk[j] * LOG2E;
            }
            // diagonal
            {
                float e0 = ex2f(wk[0] * vk[0]); z[0][e] += e0; n[0][cc][e] = e0 * vk[0];
                float e1 = ex2f(wk[1] * vk[1]); z[1][e] += e1; n[1][cc][e] = e1 * vk[1];
                float e2 = ex2f(wk[2] * vk[2]); z[2][e] += e2; n[2][cc][e] = e2 * vk[2];
                float e3 = ex2f(wk[3] * vk[3]); z[3][e] += e3; n[3][cc][e] = e3 * vk[3];
            }
            // symmetric off-diagonal
            {
                float ee;
                ee = ex2f(wk[0] * vk[1]); z[0][e] += ee; z[1][e] += ee;
                n[0][cc][e] += ee * vk[1]; n[1][cc][e] += ee * vk[0];
                ee = ex2f(wk[0] * vk[2]); z[0][e] += ee; z[2][e] += ee;
                n[0][cc][e] += ee * vk[2]; n[2][cc][e] += ee * vk[0];
                ee = ex2f(wk[0] * vk[3]); z[0][e] += ee; z[3][e] += ee;
                n[0][cc][e] += ee * vk[3]; n[3][cc][e] += ee * vk[0];
                ee = ex2f(wk[1] * vk[2]); z[1][e] += ee; z[2][e] += ee;
                n[1][cc][e] += ee * vk[2]; n[2][cc][e] += ee * vk[1];
                ee = ex2f(wk[1] * vk[3]); z[1][e] += ee; z[3][e] += ee;
                n[1][cc][e] += ee * vk[3]; n[3][cc][e] += ee * vk[1];
                ee = ex2f(wk[2] * vk[3]); z[2][e] += ee; z[3][e] += ee;
                n[2][cc][e] += ee * vk[3]; n[3][cc][e] += ee * vk[2];
            }
        }
    }

    // ---- Z reduction ----
    // Within a warp, the 4 slices sharing a pixel group q sit at lanes
    // {q, q+8, q+16, q+24}: butterfly over xor 8 and 16 sums them.
    #pragma unroll
    for (int i = 0; i < 4; ++i)
        #pragma unroll
        for (int e = 0; e < 4; ++e) {
            float s = z[i][e];
            s += __shfl_xor_sync(0xFFFFFFFFu, s, 8);
            s += __shfl_xor_sync(0xFFFFFFFFu, s, 16);
            z[i][e] = s;
        }
    if (lane < 8) {
        #pragma unroll
        for (int i = 0; i < 4; ++i)
            szp[w][i][q] = make_float4(z[i][0], z[i][1], z[i][2], z[i][3]);
    }
    __syncthreads();

    if (tid < 32) {
        const int i  = tid >> 3;
        const int qq = tid & 7;
        float4 s = szp[0][i][qq];
        #pragma unroll
        for (int ww = 1; ww < 8; ++ww) {
            float4 t = szp[ww][i][qq];
            s.x += t.x; s.y += t.y; s.z += t.z; s.w += t.w;
        }
        srz[i][qq] = make_float4(1.0f / s.x, 1.0f / s.y, 1.0f / s.z, 1.0f / s.w);
    }
    __syncthreads();

    // ---- scale + streaming vector stores: 8x STG.128 ----
    float4 rz[4];
    #pragma unroll
    for (int i = 0; i < 4; ++i) rz[i] = srz[i][q];   // broadcast LDS

    #pragma unroll
    for (int i = 0; i < 4; ++i)
        #pragma unroll
        for (int cc = 0; cc < 2; ++cc) {
            float4 o;
            o.x = n[i][cc][0] * rz[i].x;
            o.y = n[i][cc][1] * rz[i].y;
            o.z = n[i][cc][2] * rz[i].z;
            o.w = n[i][cc][3] * rz[i].w;
            float4* op = (float4*)out
                       + ((size_t)b * 256 + i * 64 + c0 + cc) * (HW_ / 4) + (p0 >> 2);
            __stcs(op, o);
        }
}

extern "C" void kernel_launch(void* const* d_in, const int* in_sizes, int n_in,
                              void* d_out, int out_size)
{
    const float* frames = (const float*)d_in[0];
    float* out = (float*)d_out;
    frame_attn_kernel<<<B_ * (HW_ / 32), NTHR>>>(frames, out);   // 6400 blocks
}

// round 11
// speedup vs baseline: 1.2996x; 1.2996x over previous
#include <cuda_runtime.h>

// frames: [4, B=8, C=64, H=160, W=160] fp32 ; out: [B, 256, H, W] fp32
// out_i[c,p] = sum_j exp(v_i[c,p]*v_j[c,p]) * v_j[c,p] / Z_i(p)
// Z_i(p) = sum_{j,c} exp(v_i[c,p]*v_j[c,p]);  symmetric in (i,j): 10 pairs.

#define HW_    25600   // 160*160
#define C_     64
#define B_     8
#define PX     32      // pixels per tile
#define NT     2       // consecutive tiles per block (cp.async pipelined)
#define NTHR   256
#define NROW   256     // 4 frames * 64 channels
#define TILE_F (NROW * PX)   // 32 KB

__device__ __forceinline__ float ex2f(float x) {
    float y;
    asm("ex2.approx.ftz.f32 %0, %1;" : "=f"(y) : "f"(x));
    return y;
}

__device__ __forceinline__ float rcpf(float x) {
    float y;
    asm("rcp.approx.ftz.f32 %0, %1;" : "=f"(y) : "f"(x));
    return y;
}

__device__ __forceinline__ unsigned smem_u32(const void* p) {
    unsigned a;
    asm("{ .reg .u64 t; cvta.to.shared.u64 t, %1; cvt.u32.u64 %0, t; }"
        : "=r"(a) : "l"(p));
    return a;
}

__global__ __launch_bounds__(NTHR, 3)
void frame_attn_kernel(const float* __restrict__ frames, float* __restrict__ out)
{
    __shared__ float sbuf[2][TILE_F];   // double-buffered input tiles
    __shared__ float szp[8][4][PX];     // per-slice partial Z
    __shared__ float srz[4][PX];        // reciprocal Z per (head, px)

    const int tid   = threadIdx.x;
    const int slice = tid >> 5;          // warp id 0..7 (8 channels each)
    const int px    = tid & 31;
    const int r0    = tid >> 3;          // load-row base (0..31)
    const int c4b   = (tid & 7) * 16;    // byte offset within 128B row chunk

    const int tile0 = blockIdx.x * NT;          // 800 tiles per b, NT=2 divides
    const int b     = tile0 / (HW_ / PX);       // same b for both tiles
    const int p0b   = (tile0 % (HW_ / PX)) * PX;

    // ---- async prefetch of one 32KB tile into sbuf[bufi] ----
    auto prefetch = [&](int p0, int bufi) {
        const char* gbase = (const char*)frames
                          + (size_t)4 * p0 + (size_t)b * C_ * HW_ * 4 + c4b;
        const unsigned sb = smem_u32(&sbuf[bufi][0]) + (unsigned)(r0 * (PX * 4) + c4b);
        #pragma unroll
        for (int it = 0; it < 8; ++it) {
            const int row = it * 32 + r0;        // 0..255 = j*64 + c
            const int j = row >> 6, c = row & 63;
            const char* g = gbase + ((size_t)j * (B_ * C_) + c) * (HW_ * 4);
            const unsigned s = sb + (unsigned)(it * 32 * PX * 4);
            asm volatile("cp.async.cg.shared.global [%0], [%1], 16;"
                         :: "r"(s), "l"(g) : "memory");
        }
        asm volatile("cp.async.commit_group;" ::: "memory");
    };

    // ---- compute + normalize + store for the tile in sbuf[bufi] ----
    auto process = [&](int p0, int bufi) {
        const float* svb = &sbuf[bufi][0] + (slice * 8) * PX + px;
        const float LOG2E = 1.4426950408889634f;

        float n[4][8];    // numerators stay in registers (no smem round-trip)
        float zp[10];
        #pragma unroll
        for (int p = 0; p < 10; ++p) zp[p] = 0.0f;

        #pragma unroll
        for (int k = 0; k < 8; ++k) {
            float vk[4], wk[4];
            #pragma unroll
            for (int j = 0; j < 4; ++j) {
                float x = svb[(j * C_ + k) * PX];
                vk[j] = x;
                wk[j] = x * LOG2E;
            }
            {   // diagonal pairs
                float e0 = ex2f(wk[0] * vk[0]); zp[0] += e0; n[0][k] = e0 * vk[0];
                float e1 = ex2f(wk[1] * vk[1]); zp[4] += e1; n[1][k] = e1 * vk[1];
                float e2 = ex2f(wk[2] * vk[2]); zp[7] += e2; n[2][k] = e2 * vk[2];
                float e3 = ex2f(wk[3] * vk[3]); zp[9] += e3; n[3][k] = e3 * vk[3];
            }
            {   // symmetric off-diagonal pairs
                float e;
                e = ex2f(wk[0] * vk[1]); zp[1] += e; n[0][k] += e * vk[1]; n[1][k] += e * vk[0];
                e = ex2f(wk[0] * vk[2]); zp[2] += e; n[0][k] += e * vk[2]; n[2][k] += e * vk[0];
                e = ex2f(wk[0] * vk[3]); zp[3] += e; n[0][k] += e * vk[3]; n[3][k] += e * vk[0];
                e = ex2f(wk[1] * vk[2]); zp[5] += e; n[1][k] += e * vk[2]; n[2][k] += e * vk[1];
                e = ex2f(wk[1] * vk[3]); zp[6] += e; n[1][k] += e * vk[3]; n[3][k] += e * vk[1];
                e = ex2f(wk[2] * vk[3]); zp[8] += e; n[2][k] += e * vk[3]; n[3][k] += e * vk[2];
            }
        }

        // pairs: (0,0)=0 (0,1)=1 (0,2)=2 (0,3)=3 (1,1)=4 (1,2)=5 (1,3)=6 (2,2)=7 (2,3)=8 (3,3)=9
        szp[slice][0][px] = zp[0] + zp[1] + zp[2] + zp[3];
        szp[slice][1][px] = zp[1] + zp[4] + zp[5] + zp[6];
        szp[slice][2][px] = zp[2] + zp[5] + zp[7] + zp[8];
        szp[slice][3][px] = zp[3] + zp[6] + zp[8] + zp[9];
        __syncthreads();

        if (slice < 4) {
            float s = 0.0f;
            #pragma unroll
            for (int s8 = 0; s8 < 8; ++s8) s += szp[s8][slice][px];
            srz[slice][px] = rcpf(s);
        }
        __syncthreads();

        // coalesced streaming stores: warp = fixed row, 32 consecutive px
        float* ob = out + ((size_t)b * 4 * C_ + slice * 8) * HW_ + p0 + px;
        #pragma unroll
        for (int i = 0; i < 4; ++i) {
            const float r = srz[i][px];
            #pragma unroll
            for (int k = 0; k < 8; ++k)
                __stcs(ob + ((size_t)i * C_ + k) * HW_, n[i][k] * r);
        }
    };

    // ---- pipelined schedule: both prefetches up front ----
    prefetch(p0b, 0);
    prefetch(p0b + PX, 1);

    asm volatile("cp.async.wait_group 1;" ::: "memory");
    __syncthreads();
    process(p0b, 0);

    asm volatile("cp.async.wait_group 0;" ::: "memory");
    __syncthreads();   // also orders tile0's szp/srz reads before tile1 rewrites
    process(p0b + PX, 1);
}

extern "C" void kernel_launch(void* const* d_in, const int* in_sizes, int n_in,
                              void* d_out, int out_size)
{
    const float* frames = (const float*)d_in[0];
    float* out = (float*)d_out;
    frame_attn_kernel<<<B_ * (HW_ / PX) / NT, NTHR>>>(frames, out);   // 3200
}